// round 8
// baseline (speedup 1.0000x reference)
#include <cuda_runtime.h>
#include <math.h>

static constexpr float EPS_CLIP = 1e-7f;
static constexpr float SCALE    = 64.0f;
// cos(0.5), sin(0.5)
static constexpr float COS_M = 0.8775825618903728f;
static constexpr float SIN_M = 0.479425538604203f;

// ---------------------------------------------------------------------------
// Single fused kernel, grid-stride: each warp processes ~8 rows.
//  - W inverse norms computed ONCE per warp (amortized over its rows):
//    8 W LDG.128 + 32 FMA + 2-value reduce, no barrier, no smem.
//  - Per row: identical to the proven R4 body — 4 feat LDG.128 (coalesced)
//    + 8 W LDG.128 (L1 hits) interleaved with 48 FMA, 3-value warp reduce,
//    margin math on lane 0.
//  - launch_bounds(256, 7) caps regs at 36 to protect occupancy (R5 lesson).
// ---------------------------------------------------------------------------
__global__ void __launch_bounds__(256, 7)
arcface_kernel(const float* __restrict__ feat,
               const float* __restrict__ W,
               const int*   __restrict__ label,
               float*       __restrict__ out,
               int B, int nwarps)
{
    const int gwarp = (blockIdx.x * blockDim.x + threadIdx.x) >> 5;
    const int lane  = threadIdx.x & 31;

    const float4* __restrict__ W4 = reinterpret_cast<const float4*>(W);

    // ---- Once per warp: inverse norms of the two W rows ----
    float sw0 = 0.0f, sw1 = 0.0f;
    #pragma unroll
    for (int k = 0; k < 4; k++) {
        const int idx = lane + 32 * k;
        float4 b = W4[idx];
        float4 c = W4[128 + idx];
        sw0 = fmaf(b.x, b.x, sw0); sw0 = fmaf(b.y, b.y, sw0);
        sw0 = fmaf(b.z, b.z, sw0); sw0 = fmaf(b.w, b.w, sw0);
        sw1 = fmaf(c.x, c.x, sw1); sw1 = fmaf(c.y, c.y, sw1);
        sw1 = fmaf(c.z, c.z, sw1); sw1 = fmaf(c.w, c.w, sw1);
    }
    #pragma unroll
    for (int o = 16; o > 0; o >>= 1) {
        sw0 += __shfl_xor_sync(0xffffffff, sw0, o);
        sw1 += __shfl_xor_sync(0xffffffff, sw1, o);
    }
    const float invw0 = 1.0f / fmaxf(sqrtf(sw0), 1e-12f);
    const float invw1 = 1.0f / fmaxf(sqrtf(sw1), 1e-12f);

    // ---- Row loop (consecutive warps -> consecutive rows each iteration) ----
    for (int row = gwarp; row < B; row += nwarps) {
        const float4* __restrict__ f =
            reinterpret_cast<const float4*>(feat + (size_t)row * 512);

        float ss = 0.0f, d0 = 0.0f, d1 = 0.0f;

        #pragma unroll
        for (int k = 0; k < 4; k++) {
            const int idx = lane + 32 * k;   // 128 float4 per row
            float4 a = f[idx];
            float4 b = W4[idx];
            float4 c = W4[128 + idx];
            ss = fmaf(a.x, a.x, ss); ss = fmaf(a.y, a.y, ss);
            ss = fmaf(a.z, a.z, ss); ss = fmaf(a.w, a.w, ss);
            d0 = fmaf(a.x, b.x, d0); d0 = fmaf(a.y, b.y, d0);
            d0 = fmaf(a.z, b.z, d0); d0 = fmaf(a.w, b.w, d0);
            d1 = fmaf(a.x, c.x, d1); d1 = fmaf(a.y, c.y, d1);
            d1 = fmaf(a.z, c.z, d1); d1 = fmaf(a.w, c.w, d1);
        }

        #pragma unroll
        for (int o = 16; o > 0; o >>= 1) {
            ss += __shfl_xor_sync(0xffffffff, ss, o);
            d0 += __shfl_xor_sync(0xffffffff, d0, o);
            d1 += __shfl_xor_sync(0xffffffff, d1, o);
        }

        if (lane == 0) {
            const float invf = 1.0f / fmaxf(sqrtf(ss), 1e-12f);

            float c0 = fminf(fmaxf(d0 * invf * invw0, -1.0f + EPS_CLIP), 1.0f - EPS_CLIP);
            float c1 = fminf(fmaxf(d1 * invf * invw1, -1.0f + EPS_CLIP), 1.0f - EPS_CLIP);

            // cos(theta + m) = cos*cos_m - sin*sin_m, sin = sqrt(1-cos^2) >= 0
            float s0 = sqrtf(fmaxf(1.0f - c0 * c0, 0.0f));
            float s1 = sqrtf(fmaxf(1.0f - c1 * c1, 0.0f));
            float m0 = c0 * COS_M - s0 * SIN_M;
            float m1 = c1 * COS_M - s1 * SIN_M;

            const int lab = label[row];
            float o0 = (lab == 0) ? m0 : c0;
            float o1 = (lab == 1) ? m1 : c1;

            reinterpret_cast<float2*>(out)[row] = make_float2(o0 * SCALE, o1 * SCALE);
        }
    }
}

// ---------------------------------------------------------------------------
// kernel_launch: identify inputs by element count (robust to ordering):
//   feat : B*D f32 (largest), W : C*D f32 (smallest), label : B int32
// ---------------------------------------------------------------------------
extern "C" void kernel_launch(void* const* d_in, const int* in_sizes, int n_in,
                              void* d_out, int out_size)
{
    int i_feat = 0, i_w = 0, i_lab = 0;
    for (int i = 1; i < n_in; i++) {
        if (in_sizes[i] > in_sizes[i_feat]) i_feat = i;
        if (in_sizes[i] < in_sizes[i_w])    i_w    = i;
    }
    for (int i = 0; i < n_in; i++)
        if (i != i_feat && i != i_w) i_lab = i;

    const float* feat  = (const float*)d_in[i_feat];
    const float* W     = (const float*)d_in[i_w];
    const int*   label = (const int*)d_in[i_lab];
    float*       out   = (float*)d_out;
    const int    B     = in_sizes[i_lab];

    const int blocks = 2048;              // 16384 warps -> 8 rows per warp
    const int nwarps = blocks * (256 / 32);
    arcface_kernel<<<blocks, 256>>>(feat, W, label, out, B, nwarps);
}

// round 9
// speedup vs baseline: 1.2280x; 1.2280x over previous
#include <cuda_runtime.h>
#include <math.h>
#include <cstdint>

static constexpr float EPS_CLIP = 1e-7f;
static constexpr float SCALE    = 64.0f;
// cos(0.5), sin(0.5)
static constexpr float COS_M = 0.8775825618903728f;
static constexpr float SIN_M = 0.479425538604203f;

// Packed f32x2 FMA: d = a*b + c elementwise on two packed floats.
// ptxas never auto-fuses this; must be explicit PTX (sm_103a FFMA2).
__device__ __forceinline__ unsigned long long ffma2(unsigned long long a,
                                                    unsigned long long b,
                                                    unsigned long long c)
{
    unsigned long long d;
    asm("fma.rn.f32x2 %0, %1, %2, %3;" : "=l"(d) : "l"(a), "l"(b), "l"(c));
    return d;
}

// Horizontal sum of a packed f32x2.
__device__ __forceinline__ float hsum2(unsigned long long p)
{
    unsigned int lo, hi;
    asm("mov.b64 {%0, %1}, %2;" : "=r"(lo), "=r"(hi) : "l"(p));
    return __uint_as_float(lo) + __uint_as_float(hi);
}

// ---------------------------------------------------------------------------
// Single fused kernel, one warp per feature row (8 rows / 256-thread block).
// All 5 accumulators (||f||^2, f.W0, f.W1, ||W0||^2, ||W1||^2) are packed
// f32x2 — 40 FFMA2 per row instead of 80 FFMA. No barrier, no smem, no
// second kernel. 12 LDG.128 per row (4 feat DRAM-streaming + 8 W L1 hits).
// ---------------------------------------------------------------------------
__global__ void __launch_bounds__(256, 7)
arcface_kernel(const float* __restrict__ feat,
               const float* __restrict__ W,
               const int*   __restrict__ label,
               float*       __restrict__ out,
               int B)
{
    const int row  = (blockIdx.x * blockDim.x + threadIdx.x) >> 5;
    const int lane = threadIdx.x & 31;
    if (row >= B) return;

    // Each ulonglong2 = 128-bit load = two packed f32x2 pairs.
    const ulonglong2* __restrict__ f =
        reinterpret_cast<const ulonglong2*>(feat + (size_t)row * 512);
    const ulonglong2* __restrict__ W2 = reinterpret_cast<const ulonglong2*>(W);

    unsigned long long ssp = 0ull, d0p = 0ull, d1p = 0ull, s0p = 0ull, s1p = 0ull;

    #pragma unroll
    for (int k = 0; k < 4; k++) {
        const int idx = lane + 32 * k;           // 128 x 16B per row
        ulonglong2 A = f[idx];
        ulonglong2 Bv = W2[idx];
        ulonglong2 Cv = W2[128 + idx];
        ssp = ffma2(A.x,  A.x,  ssp); ssp = ffma2(A.y,  A.y,  ssp);
        d0p = ffma2(A.x,  Bv.x, d0p); d0p = ffma2(A.y,  Bv.y, d0p);
        d1p = ffma2(A.x,  Cv.x, d1p); d1p = ffma2(A.y,  Cv.y, d1p);
        s0p = ffma2(Bv.x, Bv.x, s0p); s0p = ffma2(Bv.y, Bv.y, s0p);
        s1p = ffma2(Cv.x, Cv.x, s1p); s1p = ffma2(Cv.y, Cv.y, s1p);
    }

    float ss  = hsum2(ssp);
    float d0  = hsum2(d0p);
    float d1  = hsum2(d1p);
    float sw0 = hsum2(s0p);
    float sw1 = hsum2(s1p);

    #pragma unroll
    for (int o = 16; o > 0; o >>= 1) {
        ss  += __shfl_xor_sync(0xffffffff, ss,  o);
        d0  += __shfl_xor_sync(0xffffffff, d0,  o);
        d1  += __shfl_xor_sync(0xffffffff, d1,  o);
        sw0 += __shfl_xor_sync(0xffffffff, sw0, o);
        sw1 += __shfl_xor_sync(0xffffffff, sw1, o);
    }

    if (lane == 0) {
        // rsqrt path: for ss >= 1e-24, x * rsqrt(ss) == x / max(sqrt(ss),1e-12)
        // within MUFU.RSQ precision (~2e-7 rel), far inside the 1e-3 budget.
        const float invf  = rsqrtf(fmaxf(ss,  1e-24f));
        const float invw0 = rsqrtf(fmaxf(sw0, 1e-24f));
        const float invw1 = rsqrtf(fmaxf(sw1, 1e-24f));

        float c0 = fminf(fmaxf(d0 * invf * invw0, -1.0f + EPS_CLIP), 1.0f - EPS_CLIP);
        float c1 = fminf(fmaxf(d1 * invf * invw1, -1.0f + EPS_CLIP), 1.0f - EPS_CLIP);

        // cos(theta + m) = cos*cos_m - sin*sin_m, sin = sqrt(1-cos^2) >= 0
        float s0 = sqrtf(fmaxf(1.0f - c0 * c0, 0.0f));
        float s1 = sqrtf(fmaxf(1.0f - c1 * c1, 0.0f));
        float m0 = c0 * COS_M - s0 * SIN_M;
        float m1 = c1 * COS_M - s1 * SIN_M;

        const int lab = label[row];
        float o0 = (lab == 0) ? m0 : c0;
        float o1 = (lab == 1) ? m1 : c1;

        reinterpret_cast<float2*>(out)[row] = make_float2(o0 * SCALE, o1 * SCALE);
    }
}

// ---------------------------------------------------------------------------
// kernel_launch: identify inputs by element count (robust to ordering):
//   feat : B*D f32 (largest), W : C*D f32 (smallest), label : B int32
// ---------------------------------------------------------------------------
extern "C" void kernel_launch(void* const* d_in, const int* in_sizes, int n_in,
                              void* d_out, int out_size)
{
    int i_feat = 0, i_w = 0, i_lab = 0;
    for (int i = 1; i < n_in; i++) {
        if (in_sizes[i] > in_sizes[i_feat]) i_feat = i;
        if (in_sizes[i] < in_sizes[i_w])    i_w    = i;
    }
    for (int i = 0; i < n_in; i++)
        if (i != i_feat && i != i_w) i_lab = i;

    const float* feat  = (const float*)d_in[i_feat];
    const float* W     = (const float*)d_in[i_w];
    const int*   label = (const int*)d_in[i_lab];
    float*       out   = (float*)d_out;
    const int    B     = in_sizes[i_lab];

    const int blocks = (B + 7) / 8;       // 8 rows (warps) per block
    arcface_kernel<<<blocks, 256>>>(feat, W, label, out, B);
}

// round 10
// speedup vs baseline: 1.4053x; 1.1444x over previous
#include <cuda_runtime.h>
#include <math.h>

// Normalized W lives here: 2 rows x 512 cols
__device__ float g_Wn[2 * 512];

static constexpr float EPS_CLIP = 1e-7f;
static constexpr float SCALE    = 64.0f;
// cos(0.5), sin(0.5)
static constexpr float COS_M = 0.8775825618903728f;
static constexpr float SIN_M = 0.479425538604203f;

// ---------------------------------------------------------------------------
// Prologue: L2-normalize W rows (C=2, D=512) into g_Wn.
// Fires the dependent (main) kernel's launch immediately at start so the
// main grid's feat loads overlap this kernel's execution (PDL).
// ---------------------------------------------------------------------------
__global__ void normalize_w_kernel(const float* __restrict__ W) {
    // Allow the dependent kernel to start launching right away.
    asm volatile("griddepcontrol.launch_dependents;" ::: "memory");

    const int row = blockIdx.x;            // 0 or 1
    const int tid = threadIdx.x;           // 0..127
    const float* wrow = W + row * 512;

    float ss = 0.0f;
    #pragma unroll
    for (int i = tid; i < 512; i += 128) {
        float v = wrow[i];
        ss += v * v;
    }
    #pragma unroll
    for (int o = 16; o > 0; o >>= 1) ss += __shfl_xor_sync(0xffffffff, ss, o);

    __shared__ float warp_ss[4];
    __shared__ float s_inv;
    const int lane = tid & 31;
    const int wid  = tid >> 5;
    if (lane == 0) warp_ss[wid] = ss;
    __syncthreads();
    if (tid == 0) {
        float tot = warp_ss[0] + warp_ss[1] + warp_ss[2] + warp_ss[3];
        s_inv = 1.0f / fmaxf(sqrtf(tot), 1e-12f);
    }
    __syncthreads();

    const float inv = s_inv;
    #pragma unroll
    for (int i = tid; i < 512; i += 128) {
        g_Wn[row * 512 + i] = wrow[i] * inv;
    }
}

// ---------------------------------------------------------------------------
// Main: one warp per feature row (proven R4 body, 44us @ 78.8% DRAM).
// Feat loads are issued BEFORE griddepcontrol.wait so they overlap the
// prologue; g_Wn is only read after the wait.
// ---------------------------------------------------------------------------
__global__ void __launch_bounds__(256, 8)
arcface_kernel(const float* __restrict__ feat,
               const int*   __restrict__ label,
               float*       __restrict__ out,
               int B)
{
    const int row  = (blockIdx.x * blockDim.x + threadIdx.x) >> 5;
    const int lane = threadIdx.x & 31;
    if (row >= B) return;

    const float4* __restrict__ f =
        reinterpret_cast<const float4*>(feat + (size_t)row * 512);

    // Issue the 4 streaming feat loads first — overlap with prologue.
    float4 a0 = f[lane];
    float4 a1 = f[lane + 32];
    float4 a2 = f[lane + 64];
    float4 a3 = f[lane + 96];

    // Wait for normalize_w_kernel to complete (its g_Wn writes visible).
    asm volatile("griddepcontrol.wait;" ::: "memory");

    const float4* __restrict__ w0 = reinterpret_cast<const float4*>(g_Wn);
    const float4* __restrict__ w1 = reinterpret_cast<const float4*>(g_Wn + 512);

    float ss = 0.0f, d0 = 0.0f, d1 = 0.0f;

    {
        float4 b, c;
        #define ACC(A, K)                                                     \
            b = w0[lane + 32 * (K)];                                          \
            c = w1[lane + 32 * (K)];                                          \
            ss = fmaf(A.x, A.x, ss); ss = fmaf(A.y, A.y, ss);                 \
            ss = fmaf(A.z, A.z, ss); ss = fmaf(A.w, A.w, ss);                 \
            d0 = fmaf(A.x, b.x, d0); d0 = fmaf(A.y, b.y, d0);                 \
            d0 = fmaf(A.z, b.z, d0); d0 = fmaf(A.w, b.w, d0);                 \
            d1 = fmaf(A.x, c.x, d1); d1 = fmaf(A.y, c.y, d1);                 \
            d1 = fmaf(A.z, c.z, d1); d1 = fmaf(A.w, c.w, d1);
        ACC(a0, 0)
        ACC(a1, 1)
        ACC(a2, 2)
        ACC(a3, 3)
        #undef ACC
    }

    #pragma unroll
    for (int o = 16; o > 0; o >>= 1) {
        ss += __shfl_xor_sync(0xffffffff, ss, o);
        d0 += __shfl_xor_sync(0xffffffff, d0, o);
        d1 += __shfl_xor_sync(0xffffffff, d1, o);
    }

    if (lane == 0) {
        const float invf = rsqrtf(fmaxf(ss, 1e-24f));

        float c0 = fminf(fmaxf(d0 * invf, -1.0f + EPS_CLIP), 1.0f - EPS_CLIP);
        float c1 = fminf(fmaxf(d1 * invf, -1.0f + EPS_CLIP), 1.0f - EPS_CLIP);

        // cos(theta + m) = cos*cos_m - sin*sin_m, sin = sqrt(1-cos^2) >= 0
        float s0 = sqrtf(fmaxf(1.0f - c0 * c0, 0.0f));
        float s1 = sqrtf(fmaxf(1.0f - c1 * c1, 0.0f));
        float m0 = c0 * COS_M - s0 * SIN_M;
        float m1 = c1 * COS_M - s1 * SIN_M;

        const int lab = label[row];
        float o0 = (lab == 0) ? m0 : c0;
        float o1 = (lab == 1) ? m1 : c1;

        reinterpret_cast<float2*>(out)[row] = make_float2(o0 * SCALE, o1 * SCALE);
    }
}

// ---------------------------------------------------------------------------
// kernel_launch: identify inputs by element count (robust to ordering):
//   feat : B*D f32 (largest), W : C*D f32 (smallest), label : B int32
// Secondary kernel launched with Programmatic Stream Serialization so its
// launch overlaps the prologue (PDL).
// ---------------------------------------------------------------------------
extern "C" void kernel_launch(void* const* d_in, const int* in_sizes, int n_in,
                              void* d_out, int out_size)
{
    int i_feat = 0, i_w = 0, i_lab = 0;
    for (int i = 1; i < n_in; i++) {
        if (in_sizes[i] > in_sizes[i_feat]) i_feat = i;
        if (in_sizes[i] < in_sizes[i_w])    i_w    = i;
    }
    for (int i = 0; i < n_in; i++)
        if (i != i_feat && i != i_w) i_lab = i;

    const float* feat  = (const float*)d_in[i_feat];
    const float* W     = (const float*)d_in[i_w];
    const int*   label = (const int*)d_in[i_lab];
    float*       out   = (float*)d_out;
    const int    B     = in_sizes[i_lab];

    normalize_w_kernel<<<2, 128>>>(W);

    const int blocks = (B + 7) / 8;        // 8 rows (warps) per block

    cudaLaunchConfig_t cfg = {};
    cfg.gridDim  = dim3((unsigned)blocks, 1, 1);
    cfg.blockDim = dim3(256, 1, 1);
    cfg.dynamicSmemBytes = 0;
    cfg.stream = 0;                        // same (default) stream as prologue

    cudaLaunchAttribute attr[1];
    attr[0].id = cudaLaunchAttributeProgrammaticStreamSerialization;
    attr[0].val.programmaticStreamSerializationAllowed = 1;
    cfg.attrs = attr;
    cfg.numAttrs = 1;

    cudaLaunchKernelEx(&cfg, arcface_kernel, feat, label, out, B);
}